// round 1
// baseline (speedup 1.0000x reference)
#include <cuda_runtime.h>
#include <math.h>

#define Q_LEN   1024
#define KV_LEN  6404
#define HIDDEN  4096
#define NH      32
#define NKVH    8
#define HD      128
#define QKV_LDB 6144
#define KV_N    2048
#define ATTN_SCALE 0.08838834764831845f

// Scratch (device globals; no allocation allowed in kernel_launch)
__device__ float g_q[Q_LEN * HIDDEN];       // 16 MB  : Q after proj (+rmsnorm in place)
__device__ float g_kv[KV_LEN * KV_N];       // 52.5 MB: [kv, 0:1024]=K, [kv,1024:2048]=V
__device__ float g_attn[Q_LEN * HIDDEN];    // 16 MB  : attention output [q, h*128+d]

// ---------------------------------------------------------------------------
// Generic tiled fp32 GEMM: C[M,N] = A[M,K] @ B[:, bcol0 : bcol0+N]
// 128x128 tile, BK=16, 256 threads, 8x8 micro-tile per thread.
// N % 128 == 0 and K % 16 == 0 are assumed (true for all three calls).
// ---------------------------------------------------------------------------
__global__ void __launch_bounds__(256) gemm_kernel(
    const float* __restrict__ A, const float* __restrict__ B, float* __restrict__ C,
    int M, int K, int lda, int ldb, int ldc, int bcol0)
{
    __shared__ float As[16][128];
    __shared__ float Bs[16][128];
    const int tid = threadIdx.x;
    const int tx = tid & 15, ty = tid >> 4;
    const int row0 = blockIdx.y * 128, col0 = blockIdx.x * 128;

    float acc[8][8];
#pragma unroll
    for (int i = 0; i < 8; i++)
#pragma unroll
        for (int j = 0; j < 8; j++) acc[i][j] = 0.f;

    for (int k0 = 0; k0 < K; k0 += 16) {
        // Load A tile 128x16 (transposed into As[k][m]); 2 float4 per thread
#pragma unroll
        for (int i = 0; i < 2; i++) {
            int f = tid * 2 + i;          // 0..511
            int r = f >> 2;               // 0..127
            int kq = (f & 3) << 2;        // 0,4,8,12
            float4 v = make_float4(0.f, 0.f, 0.f, 0.f);
            if (row0 + r < M)
                v = *(const float4*)(A + (size_t)(row0 + r) * lda + k0 + kq);
            As[kq + 0][r] = v.x; As[kq + 1][r] = v.y;
            As[kq + 2][r] = v.z; As[kq + 3][r] = v.w;
        }
        // Load B tile 16x128
#pragma unroll
        for (int i = 0; i < 2; i++) {
            int f = tid * 2 + i;
            int kr = f >> 5;              // 0..15
            int c = (f & 31) << 2;        // 0..124
            *(float4*)&Bs[kr][c] =
                *(const float4*)(B + (size_t)(k0 + kr) * ldb + bcol0 + col0 + c);
        }
        __syncthreads();
#pragma unroll
        for (int kk = 0; kk < 16; kk++) {
            float a[8], b[8];
            *(float4*)&a[0] = *(float4*)&As[kk][ty * 8];
            *(float4*)&a[4] = *(float4*)&As[kk][ty * 8 + 4];
            *(float4*)&b[0] = *(float4*)&Bs[kk][tx * 8];
            *(float4*)&b[4] = *(float4*)&Bs[kk][tx * 8 + 4];
#pragma unroll
            for (int i = 0; i < 8; i++)
#pragma unroll
                for (int j = 0; j < 8; j++)
                    acc[i][j] = fmaf(a[i], b[j], acc[i][j]);
        }
        __syncthreads();
    }

#pragma unroll
    for (int i = 0; i < 8; i++) {
        int r = row0 + ty * 8 + i;
        if (r < M) {
            *(float4*)(C + (size_t)r * ldc + col0 + tx * 8)     =
                make_float4(acc[i][0], acc[i][1], acc[i][2], acc[i][3]);
            *(float4*)(C + (size_t)r * ldc + col0 + tx * 8 + 4) =
                make_float4(acc[i][4], acc[i][5], acc[i][6], acc[i][7]);
        }
    }
}

// ---------------------------------------------------------------------------
// RMS norm over last dim (128) per (row, head), in place. One warp per pair.
// ---------------------------------------------------------------------------
__global__ void rmsnorm_kernel(float* __restrict__ x, const float* __restrict__ w,
                               int nrows, int nheads, int ld)
{
    int gw = (int)((blockIdx.x * blockDim.x + threadIdx.x) >> 5);
    int lane = threadIdx.x & 31;
    if (gw >= nrows * nheads) return;
    int row = gw / nheads, h = gw - row * nheads;
    float* p = x + (size_t)row * ld + h * HD;
    float4 v = *(float4*)(p + lane * 4);
    float ss = v.x * v.x + v.y * v.y + v.z * v.z + v.w * v.w;
#pragma unroll
    for (int o = 16; o > 0; o >>= 1) ss += __shfl_xor_sync(0xffffffffu, ss, o);
    float s = rsqrtf(ss * (1.f / HD) + 1e-5f);
    float4 wv = *(const float4*)(w + lane * 4);
    v.x *= s * wv.x; v.y *= s * wv.y; v.z *= s * wv.z; v.w *= s * wv.w;
    *(float4*)(p + lane * 4) = v;
}

// ---------------------------------------------------------------------------
// Flash attention, fp32, online softmax.
// Grid: (q_tiles=16, heads=32). Block 256 threads.
// Tiles: Q 64x128 (resident), K/V 64x128 per chunk.
// S phase: thread tile 4 rows x 4 cols (cols c, c+16, c+32, c+48).
// PV phase: thread tile 2 rows x 16 d (d = 4*dg + 32*t, t=0..3).
// Row state (m, l, rescale factor) in shared memory.
// ---------------------------------------------------------------------------
#define KROW 132              // padded row stride in smem (floats)

__global__ void __launch_bounds__(256) attn_kernel(const float* __restrict__ mask)
{
    extern __shared__ float sm[];
    float* Qs = sm;                      // 64*132
    float* Ks = Qs + 64 * KROW;          // 64*132
    float* Vs = Ks + 64 * KROW;          // 64*132
    float* Ps = Vs + 64 * KROW;          // 64*65
    float* Ms = Ps + 64 * 65;            // 64
    float* Ls = Ms + 64;                 // 64
    float* Fs = Ls + 64;                 // 64

    const int tid = threadIdx.x;
    const int h = blockIdx.y;
    const int kvh = h >> 2;
    const int q0 = blockIdx.x * 64;

    // Load Q tile (stays resident)
    for (int idx = tid; idx < 64 * 32; idx += 256) {
        int r = idx >> 5, c4 = (idx & 31) << 2;
        *(float4*)&Qs[r * KROW + c4] =
            *(const float4*)(g_q + (size_t)(q0 + r) * HIDDEN + h * HD + c4);
    }
    if (tid < 64) { Ms[tid] = -1e30f; Ls[tid] = 0.f; Fs[tid] = 1.f; }

    // S-phase mapping
    const int sc = tid & 15;            // base col; cols are sc + 16*j
    const int sr = (tid >> 4) << 2;     // base row (4 rows)
    // PV mapping
    const int dg = tid & 7;
    const int rp = tid >> 3;            // 0..31
    const int pr0 = rp * 2, pr1 = rp * 2 + 1;

    float4 o0[4], o1[4];
#pragma unroll
    for (int t = 0; t < 4; t++) {
        o0[t] = make_float4(0.f, 0.f, 0.f, 0.f);
        o1[t] = make_float4(0.f, 0.f, 0.f, 0.f);
    }

    for (int kv0 = 0; kv0 < KV_LEN; kv0 += 64) {
        __syncthreads();   // previous PV done (and Q-load/init on first iter)

        // Load K, V chunks
        for (int idx = tid; idx < 64 * 32; idx += 256) {
            int r = idx >> 5, c4 = (idx & 31) << 2;
            float4 kvv = make_float4(0.f, 0.f, 0.f, 0.f), vvv = kvv;
            if (kv0 + r < KV_LEN) {
                const float* base = g_kv + (size_t)(kv0 + r) * KV_N;
                kvv = *(const float4*)(base + kvh * HD + c4);
                vvv = *(const float4*)(base + NKVH * HD + kvh * HD + c4);
            }
            *(float4*)&Ks[r * KROW + c4] = kvv;
            *(float4*)&Vs[r * KROW + c4] = vvv;
        }
        __syncthreads();

        // ---- S = Q @ K^T ----
        float s[4][4];
#pragma unroll
        for (int i = 0; i < 4; i++)
#pragma unroll
            for (int j = 0; j < 4; j++) s[i][j] = 0.f;

#pragma unroll 8
        for (int db = 0; db < 32; db++) {
            float4 q4[4], k4[4];
#pragma unroll
            for (int i = 0; i < 4; i++)
                q4[i] = *(float4*)&Qs[(sr + i) * KROW + db * 4];
#pragma unroll
            for (int j = 0; j < 4; j++)
                k4[j] = *(float4*)&Ks[(sc + 16 * j) * KROW + db * 4];
#pragma unroll
            for (int i = 0; i < 4; i++)
#pragma unroll
                for (int j = 0; j < 4; j++)
                    s[i][j] += q4[i].x * k4[j].x + q4[i].y * k4[j].y
                             + q4[i].z * k4[j].z + q4[i].w * k4[j].w;
        }

        // scale + mask + bounds, row max
        float mold[4], rmax[4];
#pragma unroll
        for (int i = 0; i < 4; i++) mold[i] = Ms[sr + i];
#pragma unroll
        for (int i = 0; i < 4; i++) {
            float mx = -1e30f;
#pragma unroll
            for (int j = 0; j < 4; j++) {
                int col = kv0 + sc + 16 * j;
                if (col < KV_LEN)
                    s[i][j] = s[i][j] * ATTN_SCALE
                            + mask[(size_t)(q0 + sr + i) * KV_LEN + col];
                else
                    s[i][j] = -1e30f;
                mx = fmaxf(mx, s[i][j]);
            }
            rmax[i] = mx;
        }
#pragma unroll
        for (int o = 1; o < 16; o <<= 1)
#pragma unroll
            for (int i = 0; i < 4; i++)
                rmax[i] = fmaxf(rmax[i], __shfl_xor_sync(0xffffffffu, rmax[i], o));

        float rsum[4], mnew[4];
#pragma unroll
        for (int i = 0; i < 4; i++) {
            float mn = fmaxf(mold[i], rmax[i]);
            mnew[i] = mn;
            float sum = 0.f;
#pragma unroll
            for (int j = 0; j < 4; j++) {
                float p = __expf(s[i][j] - mn);
                Ps[(sr + i) * 65 + sc + 16 * j] = p;
                sum += p;
            }
            rsum[i] = sum;
        }
#pragma unroll
        for (int o = 1; o < 16; o <<= 1)
#pragma unroll
            for (int i = 0; i < 4; i++)
                rsum[i] += __shfl_xor_sync(0xffffffffu, rsum[i], o);

        if (sc == 0) {
#pragma unroll
            for (int i = 0; i < 4; i++) {
                float f = __expf(mold[i] - mnew[i]);
                Fs[sr + i] = f;
                Ls[sr + i] = Ls[sr + i] * f + rsum[i];
                Ms[sr + i] = mnew[i];
            }
        }
        __syncthreads();

        // ---- PV: O = O*f + P @ V ----
        float f0 = Fs[pr0], f1 = Fs[pr1];
#pragma unroll
        for (int t = 0; t < 4; t++) {
            o0[t].x *= f0; o0[t].y *= f0; o0[t].z *= f0; o0[t].w *= f0;
            o1[t].x *= f1; o1[t].y *= f1; o1[t].z *= f1; o1[t].w *= f1;
        }
#pragma unroll 4
        for (int j = 0; j < 64; j++) {
            float p0 = Ps[pr0 * 65 + j];
            float p1 = Ps[pr1 * 65 + j];
#pragma unroll
            for (int t = 0; t < 4; t++) {
                float4 v = *(float4*)&Vs[j * KROW + dg * 4 + t * 32];
                o0[t].x += p0 * v.x; o0[t].y += p0 * v.y;
                o0[t].z += p0 * v.z; o0[t].w += p0 * v.w;
                o1[t].x += p1 * v.x; o1[t].y += p1 * v.y;
                o1[t].z += p1 * v.z; o1[t].w += p1 * v.w;
            }
        }
    }

    // Finalize
    float il0 = 1.f / Ls[pr0];
    float il1 = 1.f / Ls[pr1];
#pragma unroll
    for (int t = 0; t < 4; t++) {
        float4 a = o0[t];
        a.x *= il0; a.y *= il0; a.z *= il0; a.w *= il0;
        *(float4*)&g_attn[(size_t)(q0 + pr0) * HIDDEN + h * HD + dg * 4 + t * 32] = a;
        float4 b = o1[t];
        b.x *= il1; b.y *= il1; b.z *= il1; b.w *= il1;
        *(float4*)&g_attn[(size_t)(q0 + pr1) * HIDDEN + h * HD + dg * 4 + t * 32] = b;
    }
}

// ---------------------------------------------------------------------------
extern "C" void kernel_launch(void* const* d_in, const int* in_sizes, int n_in,
                              void* d_out, int out_size)
{
    const float* hidden = (const float*)d_in[0];
    const float* cross  = (const float*)d_in[1];
    const float* mask   = (const float*)d_in[2];
    const float* w_qkv  = (const float*)d_in[3];
    const float* w_o    = (const float*)d_in[4];
    const float* q_norm = (const float*)d_in[5];
    const float* k_norm = (const float*)d_in[6];
    float* out = (float*)d_out;
    (void)in_sizes; (void)n_in; (void)out_size;

    float *pq, *pkv, *pattn;
    cudaGetSymbolAddress((void**)&pq,    g_q);
    cudaGetSymbolAddress((void**)&pkv,   g_kv);
    cudaGetSymbolAddress((void**)&pattn, g_attn);

    // 1) Q projection: [1024,4096] = hidden @ w_qkv[:, 0:4096]
    gemm_kernel<<<dim3(HIDDEN / 128, Q_LEN / 128), 256>>>(
        hidden, w_qkv, pq, Q_LEN, HIDDEN, HIDDEN, QKV_LDB, HIDDEN, 0);

    // 2) KV projection: [6404,2048] = cross @ w_qkv[:, 4096:6144]
    gemm_kernel<<<dim3(KV_N / 128, (KV_LEN + 127) / 128), 256>>>(
        cross, w_qkv, pkv, KV_LEN, HIDDEN, HIDDEN, QKV_LDB, KV_N, NH * HD);

    // 3) RMS norm Q (1024 rows x 32 heads), one warp each
    {
        int nwarps = Q_LEN * NH;
        rmsnorm_kernel<<<(nwarps * 32 + 255) / 256, 256>>>(pq, q_norm, Q_LEN, NH, HIDDEN);
    }
    // 4) RMS norm K (6404 rows x 8 heads) — K occupies cols [0,1024) of g_kv
    {
        int nwarps = KV_LEN * NKVH;
        rmsnorm_kernel<<<(nwarps * 32 + 255) / 256, 256>>>(pkv, k_norm, KV_LEN, NKVH, KV_N);
    }

    // 5) Attention
    {
        size_t smem = (size_t)(3 * 64 * KROW + 64 * 65 + 3 * 64) * sizeof(float);
        cudaFuncSetAttribute(attn_kernel, cudaFuncAttributeMaxDynamicSharedMemorySize,
                             (int)smem);
        attn_kernel<<<dim3(Q_LEN / 64, NH), 256, smem>>>(mask);
    }

    // 6) Output projection: [1024,4096] = attn @ w_o
    gemm_kernel<<<dim3(HIDDEN / 128, Q_LEN / 128), 256>>>(
        pattn, w_o, out, Q_LEN, HIDDEN, HIDDEN, HIDDEN, HIDDEN, 0);
}

// round 2
// speedup vs baseline: 1.3163x; 1.3163x over previous
#include <cuda_runtime.h>
#include <cuda_bf16.h>
#include <math.h>

#define Q_LEN   1024
#define KV_LEN  6404
#define HIDDEN  4096
#define NH      32
#define NKVH    8
#define HD      128
#define QKV_LDB 6144
#define KV_N    2048
#define ATTN_SCALE 0.08838834764831845f

// ---------------- scratch (device globals; no allocs allowed) ----------------
__device__ float g_q[Q_LEN * HIDDEN];
__device__ float g_kv[KV_LEN * KV_N];
__device__ float g_attn[Q_LEN * HIDDEN];

__device__ __nv_bfloat16 g_hid_hi[Q_LEN * HIDDEN];
__device__ __nv_bfloat16 g_hid_lo[Q_LEN * HIDDEN];
__device__ __nv_bfloat16 g_cross_hi[KV_LEN * HIDDEN];
__device__ __nv_bfloat16 g_cross_lo[KV_LEN * HIDDEN];
__device__ __nv_bfloat16 g_wqkv_hi[HIDDEN * QKV_LDB];
__device__ __nv_bfloat16 g_wqkv_lo[HIDDEN * QKV_LDB];
__device__ __nv_bfloat16 g_wo_hi[HIDDEN * HIDDEN];
__device__ __nv_bfloat16 g_wo_lo[HIDDEN * HIDDEN];
__device__ __nv_bfloat16 g_attn_hi[Q_LEN * HIDDEN];
__device__ __nv_bfloat16 g_attn_lo[Q_LEN * HIDDEN];

// ---------------- fp32 -> bf16 hi/lo split ----------------
__global__ void split_kernel(const float* __restrict__ x,
                             __nv_bfloat16* __restrict__ hi,
                             __nv_bfloat16* __restrict__ lo, int n4)
{
    int i = blockIdx.x * blockDim.x + threadIdx.x;
    if (i >= n4) return;
    float4 v = ((const float4*)x)[i];
    float f[4] = {v.x, v.y, v.z, v.w};
    unsigned h[4], l[4];
#pragma unroll
    for (int j = 0; j < 4; j++) {
        __nv_bfloat16 hb = __float2bfloat16(f[j]);
        __nv_bfloat16 lb = __float2bfloat16(f[j] - __bfloat162float(hb));
        h[j] = (unsigned)__bfloat16_as_ushort(hb);
        l[j] = (unsigned)__bfloat16_as_ushort(lb);
    }
    uint2 uh, ul;
    uh.x = h[0] | (h[1] << 16); uh.y = h[2] | (h[3] << 16);
    ul.x = l[0] | (l[1] << 16); ul.y = l[2] | (l[3] << 16);
    ((uint2*)hi)[i] = uh;
    ((uint2*)lo)[i] = ul;
}

// ---------------------------------------------------------------------------
// bf16x3 tensor-core GEMM: C[M,N] = A[M,K] @ B[:, bcol0:bcol0+N]  (fp32-ish)
// Block 128x128, BK=32, 256 threads (8 warps, 2(M) x 4(N)), warp tile 64x32.
// mma.sync.m16n8k16 bf16; acc = Ahi*Bhi + Alo*Bhi + Ahi*Blo.
// ---------------------------------------------------------------------------
#define AS_STRIDE 40    // halves per A smem row (128 rows x 32 k, padded)
#define BS_STRIDE 136   // halves per B smem row (32 k rows x 128 n, padded)

#define MMA_BF16(d, a, b)                                                      \
    asm volatile(                                                              \
        "mma.sync.aligned.m16n8k16.row.col.f32.bf16.bf16.f32 "                 \
        "{%0,%1,%2,%3},{%4,%5,%6,%7},{%8,%9},{%0,%1,%2,%3};"                   \
        : "+f"((d)[0]), "+f"((d)[1]), "+f"((d)[2]), "+f"((d)[3])               \
        : "r"((a)[0]), "r"((a)[1]), "r"((a)[2]), "r"((a)[3]),                  \
          "r"((b)[0]), "r"((b)[1]))

__global__ void __launch_bounds__(256) gemm_bf16x3(
    const __nv_bfloat16* __restrict__ Ahi, const __nv_bfloat16* __restrict__ Alo,
    const __nv_bfloat16* __restrict__ Bhi, const __nv_bfloat16* __restrict__ Blo,
    float* __restrict__ C, int M, int K, int ldb, int ldc, int bcol0)
{
    __shared__ __nv_bfloat16 As[2][128 * AS_STRIDE];
    __shared__ __nv_bfloat16 Bs[2][32 * BS_STRIDE];

    const int tid  = threadIdx.x;
    const int warp = tid >> 5, lane = tid & 31;
    const int g = lane >> 2, tig = lane & 3;
    const int wm = warp & 1, wn = warp >> 1;       // 2 x 4 warp grid
    const int row0 = blockIdx.y * 128, col0 = blockIdx.x * 128;
    const int rowbase = wm * 64, colbase = wn * 32;

    float acc[4][4][4];
#pragma unroll
    for (int i = 0; i < 4; i++)
#pragma unroll
        for (int j = 0; j < 4; j++)
#pragma unroll
            for (int t = 0; t < 4; t++) acc[i][j][t] = 0.f;

    const unsigned short* Bsu0 = (const unsigned short*)Bs[0];
    const unsigned short* Bsu1 = (const unsigned short*)Bs[1];

    for (int k0 = 0; k0 < K; k0 += 32) {
        // ---- load A tiles (hi & lo), 128x32 halves each ----
#pragma unroll
        for (int i = 0; i < 2; i++) {
            int f = tid * 2 + i;              // 0..511
            int r = f >> 2;                   // 0..127
            int kq = (f & 3) * 8;             // 0,8,16,24
            uint4 vh = make_uint4(0, 0, 0, 0), vl = vh;
            if (row0 + r < M) {
                size_t off = (size_t)(row0 + r) * K + k0 + kq;
                vh = *(const uint4*)(Ahi + off);
                vl = *(const uint4*)(Alo + off);
            }
            *(uint4*)&As[0][r * AS_STRIDE + kq] = vh;
            *(uint4*)&As[1][r * AS_STRIDE + kq] = vl;
        }
        // ---- load B tiles (hi & lo), 32x128 halves each, k-major ----
#pragma unroll
        for (int i = 0; i < 2; i++) {
            int f = tid * 2 + i;
            int kr = f >> 4;                  // 0..31
            int c = (f & 15) * 8;             // 0..120
            size_t off = (size_t)(k0 + kr) * ldb + bcol0 + col0 + c;
            *(uint4*)&Bs[0][kr * BS_STRIDE + c] = *(const uint4*)(Bhi + off);
            *(uint4*)&Bs[1][kr * BS_STRIDE + c] = *(const uint4*)(Blo + off);
        }
        __syncthreads();

#pragma unroll
        for (int ks = 0; ks < 32; ks += 16) {
            unsigned ah[4][4], al[4][4], bh[4][2], bl[4][2];
#pragma unroll
            for (int am = 0; am < 4; am++) {
                int r = rowbase + am * 16 + g;
                int cb = ks + tig * 2;
                ah[am][0] = *(const unsigned*)&As[0][r * AS_STRIDE + cb];
                ah[am][1] = *(const unsigned*)&As[0][(r + 8) * AS_STRIDE + cb];
                ah[am][2] = *(const unsigned*)&As[0][r * AS_STRIDE + cb + 8];
                ah[am][3] = *(const unsigned*)&As[0][(r + 8) * AS_STRIDE + cb + 8];
                al[am][0] = *(const unsigned*)&As[1][r * AS_STRIDE + cb];
                al[am][1] = *(const unsigned*)&As[1][(r + 8) * AS_STRIDE + cb];
                al[am][2] = *(const unsigned*)&As[1][r * AS_STRIDE + cb + 8];
                al[am][3] = *(const unsigned*)&As[1][(r + 8) * AS_STRIDE + cb + 8];
            }
#pragma unroll
            for (int an = 0; an < 4; an++) {
                int n = colbase + an * 8 + g;
                int kf = ks + tig * 2;
                unsigned x0 = Bsu0[kf * BS_STRIDE + n];
                unsigned x1 = Bsu0[(kf + 1) * BS_STRIDE + n];
                unsigned x2 = Bsu0[(kf + 8) * BS_STRIDE + n];
                unsigned x3 = Bsu0[(kf + 9) * BS_STRIDE + n];
                bh[an][0] = x0 | (x1 << 16);
                bh[an][1] = x2 | (x3 << 16);
                unsigned y0 = Bsu1[kf * BS_STRIDE + n];
                unsigned y1 = Bsu1[(kf + 1) * BS_STRIDE + n];
                unsigned y2 = Bsu1[(kf + 8) * BS_STRIDE + n];
                unsigned y3 = Bsu1[(kf + 9) * BS_STRIDE + n];
                bl[an][0] = y0 | (y1 << 16);
                bl[an][1] = y2 | (y3 << 16);
            }
#pragma unroll
            for (int am = 0; am < 4; am++)
#pragma unroll
                for (int an = 0; an < 4; an++) MMA_BF16(acc[am][an], ah[am], bh[an]);
#pragma unroll
            for (int am = 0; am < 4; am++)
#pragma unroll
                for (int an = 0; an < 4; an++) MMA_BF16(acc[am][an], al[am], bh[an]);
#pragma unroll
            for (int am = 0; am < 4; am++)
#pragma unroll
                for (int an = 0; an < 4; an++) MMA_BF16(acc[am][an], ah[am], bl[an]);
        }
        __syncthreads();
    }

    // ---- epilogue ----
#pragma unroll
    for (int am = 0; am < 4; am++) {
#pragma unroll
        for (int an = 0; an < 4; an++) {
            int r = row0 + rowbase + am * 16 + g;
            int c = col0 + colbase + an * 8 + tig * 2;
            if (r < M)
                *(float2*)(C + (size_t)r * ldc + c) =
                    make_float2(acc[am][an][0], acc[am][an][1]);
            if (r + 8 < M)
                *(float2*)(C + (size_t)(r + 8) * ldc + c) =
                    make_float2(acc[am][an][2], acc[am][an][3]);
        }
    }
}

// ---------------- RMS norm (unchanged) ----------------
__global__ void rmsnorm_kernel(float* __restrict__ x, const float* __restrict__ w,
                               int nrows, int nheads, int ld)
{
    int gw = (int)((blockIdx.x * blockDim.x + threadIdx.x) >> 5);
    int lane = threadIdx.x & 31;
    if (gw >= nrows * nheads) return;
    int row = gw / nheads, h = gw - row * nheads;
    float* p = x + (size_t)row * ld + h * HD;
    float4 v = *(float4*)(p + lane * 4);
    float ss = v.x * v.x + v.y * v.y + v.z * v.z + v.w * v.w;
#pragma unroll
    for (int o = 16; o > 0; o >>= 1) ss += __shfl_xor_sync(0xffffffffu, ss, o);
    float s = rsqrtf(ss * (1.f / HD) + 1e-5f);
    float4 wv = *(const float4*)(w + lane * 4);
    v.x *= s * wv.x; v.y *= s * wv.y; v.z *= s * wv.z; v.w *= s * wv.w;
    *(float4*)(p + lane * 4) = v;
}

// ---------------- fp32 flash attention (unchanged) ----------------
#define KROW 132

__global__ void __launch_bounds__(256) attn_kernel(const float* __restrict__ mask)
{
    extern __shared__ float sm[];
    float* Qs = sm;
    float* Ks = Qs + 64 * KROW;
    float* Vs = Ks + 64 * KROW;
    float* Ps = Vs + 64 * KROW;
    float* Ms = Ps + 64 * 65;
    float* Ls = Ms + 64;
    float* Fs = Ls + 64;

    const int tid = threadIdx.x;
    const int h = blockIdx.y;
    const int kvh = h >> 2;
    const int q0 = blockIdx.x * 64;

    for (int idx = tid; idx < 64 * 32; idx += 256) {
        int r = idx >> 5, c4 = (idx & 31) << 2;
        *(float4*)&Qs[r * KROW + c4] =
            *(const float4*)(g_q + (size_t)(q0 + r) * HIDDEN + h * HD + c4);
    }
    if (tid < 64) { Ms[tid] = -1e30f; Ls[tid] = 0.f; Fs[tid] = 1.f; }

    const int sc = tid & 15;
    const int sr = (tid >> 4) << 2;
    const int dg = tid & 7;
    const int rp = tid >> 3;
    const int pr0 = rp * 2, pr1 = rp * 2 + 1;

    float4 o0[4], o1[4];
#pragma unroll
    for (int t = 0; t < 4; t++) {
        o0[t] = make_float4(0.f, 0.f, 0.f, 0.f);
        o1[t] = make_float4(0.f, 0.f, 0.f, 0.f);
    }

    for (int kv0 = 0; kv0 < KV_LEN; kv0 += 64) {
        __syncthreads();
        for (int idx = tid; idx < 64 * 32; idx += 256) {
            int r = idx >> 5, c4 = (idx & 31) << 2;
            float4 kvv = make_float4(0.f, 0.f, 0.f, 0.f), vvv = kvv;
            if (kv0 + r < KV_LEN) {
                const float* base = g_kv + (size_t)(kv0 + r) * KV_N;
                kvv = *(const float4*)(base + kvh * HD + c4);
                vvv = *(const float4*)(base + NKVH * HD + kvh * HD + c4);
            }
            *(float4*)&Ks[r * KROW + c4] = kvv;
            *(float4*)&Vs[r * KROW + c4] = vvv;
        }
        __syncthreads();

        float s[4][4];
#pragma unroll
        for (int i = 0; i < 4; i++)
#pragma unroll
            for (int j = 0; j < 4; j++) s[i][j] = 0.f;

#pragma unroll 8
        for (int db = 0; db < 32; db++) {
            float4 q4[4], k4[4];
#pragma unroll
            for (int i = 0; i < 4; i++)
                q4[i] = *(float4*)&Qs[(sr + i) * KROW + db * 4];
#pragma unroll
            for (int j = 0; j < 4; j++)
                k4[j] = *(float4*)&Ks[(sc + 16 * j) * KROW + db * 4];
#pragma unroll
            for (int i = 0; i < 4; i++)
#pragma unroll
                for (int j = 0; j < 4; j++)
                    s[i][j] += q4[i].x * k4[j].x + q4[i].y * k4[j].y
                             + q4[i].z * k4[j].z + q4[i].w * k4[j].w;
        }

        float mold[4], rmax[4];
#pragma unroll
        for (int i = 0; i < 4; i++) mold[i] = Ms[sr + i];
#pragma unroll
        for (int i = 0; i < 4; i++) {
            float mx = -1e30f;
#pragma unroll
            for (int j = 0; j < 4; j++) {
                int col = kv0 + sc + 16 * j;
                if (col < KV_LEN)
                    s[i][j] = s[i][j] * ATTN_SCALE
                            + mask[(size_t)(q0 + sr + i) * KV_LEN + col];
                else
                    s[i][j] = -1e30f;
                mx = fmaxf(mx, s[i][j]);
            }
            rmax[i] = mx;
        }
#pragma unroll
        for (int o = 1; o < 16; o <<= 1)
#pragma unroll
            for (int i = 0; i < 4; i++)
                rmax[i] = fmaxf(rmax[i], __shfl_xor_sync(0xffffffffu, rmax[i], o));

        float rsum[4], mnew[4];
#pragma unroll
        for (int i = 0; i < 4; i++) {
            float mn = fmaxf(mold[i], rmax[i]);
            mnew[i] = mn;
            float sum = 0.f;
#pragma unroll
            for (int j = 0; j < 4; j++) {
                float p = __expf(s[i][j] - mn);
                Ps[(sr + i) * 65 + sc + 16 * j] = p;
                sum += p;
            }
            rsum[i] = sum;
        }
#pragma unroll
        for (int o = 1; o < 16; o <<= 1)
#pragma unroll
            for (int i = 0; i < 4; i++)
                rsum[i] += __shfl_xor_sync(0xffffffffu, rsum[i], o);

        if (sc == 0) {
#pragma unroll
            for (int i = 0; i < 4; i++) {
                float f = __expf(mold[i] - mnew[i]);
                Fs[sr + i] = f;
                Ls[sr + i] = Ls[sr + i] * f + rsum[i];
                Ms[sr + i] = mnew[i];
            }
        }
        __syncthreads();

        float f0 = Fs[pr0], f1 = Fs[pr1];
#pragma unroll
        for (int t = 0; t < 4; t++) {
            o0[t].x *= f0; o0[t].y *= f0; o0[t].z *= f0; o0[t].w *= f0;
            o1[t].x *= f1; o1[t].y *= f1; o1[t].z *= f1; o1[t].w *= f1;
        }
#pragma unroll 4
        for (int j = 0; j < 64; j++) {
            float p0 = Ps[pr0 * 65 + j];
            float p1 = Ps[pr1 * 65 + j];
#pragma unroll
            for (int t = 0; t < 4; t++) {
                float4 v = *(float4*)&Vs[j * KROW + dg * 4 + t * 32];
                o0[t].x += p0 * v.x; o0[t].y += p0 * v.y;
                o0[t].z += p0 * v.z; o0[t].w += p0 * v.w;
                o1[t].x += p1 * v.x; o1[t].y += p1 * v.y;
                o1[t].z += p1 * v.z; o1[t].w += p1 * v.w;
            }
        }
    }

    float il0 = 1.f / Ls[pr0];
    float il1 = 1.f / Ls[pr1];
#pragma unroll
    for (int t = 0; t < 4; t++) {
        float4 a = o0[t];
        a.x *= il0; a.y *= il0; a.z *= il0; a.w *= il0;
        *(float4*)&g_attn[(size_t)(q0 + pr0) * HIDDEN + h * HD + dg * 4 + t * 32] = a;
        float4 b = o1[t];
        b.x *= il1; b.y *= il1; b.z *= il1; b.w *= il1;
        *(float4*)&g_attn[(size_t)(q0 + pr1) * HIDDEN + h * HD + dg * 4 + t * 32] = b;
    }
}

// ---------------------------------------------------------------------------
extern "C" void kernel_launch(void* const* d_in, const int* in_sizes, int n_in,
                              void* d_out, int out_size)
{
    const float* hidden = (const float*)d_in[0];
    const float* cross  = (const float*)d_in[1];
    const float* mask   = (const float*)d_in[2];
    const float* w_qkv  = (const float*)d_in[3];
    const float* w_o    = (const float*)d_in[4];
    const float* q_norm = (const float*)d_in[5];
    const float* k_norm = (const float*)d_in[6];
    float* out = (float*)d_out;
    (void)in_sizes; (void)n_in; (void)out_size;

    float *pq, *pkv, *pattn;
    cudaGetSymbolAddress((void**)&pq,    g_q);
    cudaGetSymbolAddress((void**)&pkv,   g_kv);
    cudaGetSymbolAddress((void**)&pattn, g_attn);
    __nv_bfloat16 *hid_hi, *hid_lo, *cross_hi, *cross_lo, *wqkv_hi, *wqkv_lo,
                  *wo_hi, *wo_lo, *attn_hi, *attn_lo;
    cudaGetSymbolAddress((void**)&hid_hi,   g_hid_hi);
    cudaGetSymbolAddress((void**)&hid_lo,   g_hid_lo);
    cudaGetSymbolAddress((void**)&cross_hi, g_cross_hi);
    cudaGetSymbolAddress((void**)&cross_lo, g_cross_lo);
    cudaGetSymbolAddress((void**)&wqkv_hi,  g_wqkv_hi);
    cudaGetSymbolAddress((void**)&wqkv_lo,  g_wqkv_lo);
    cudaGetSymbolAddress((void**)&wo_hi,    g_wo_hi);
    cudaGetSymbolAddress((void**)&wo_lo,    g_wo_lo);
    cudaGetSymbolAddress((void**)&attn_hi,  g_attn_hi);
    cudaGetSymbolAddress((void**)&attn_lo,  g_attn_lo);

    // ---- splits ----
    {
        int n4;
        n4 = Q_LEN * HIDDEN / 4;
        split_kernel<<<(n4 + 255) / 256, 256>>>(hidden, hid_hi, hid_lo, n4);
        n4 = KV_LEN * HIDDEN / 4;
        split_kernel<<<(n4 + 255) / 256, 256>>>(cross, cross_hi, cross_lo, n4);
        n4 = HIDDEN * QKV_LDB / 4;
        split_kernel<<<(n4 + 255) / 256, 256>>>(w_qkv, wqkv_hi, wqkv_lo, n4);
        n4 = HIDDEN * HIDDEN / 4;
        split_kernel<<<(n4 + 255) / 256, 256>>>(w_o, wo_hi, wo_lo, n4);
    }

    // ---- Q projection: [1024,4096] ----
    gemm_bf16x3<<<dim3(HIDDEN / 128, Q_LEN / 128), 256>>>(
        hid_hi, hid_lo, wqkv_hi, wqkv_lo, pq,
        Q_LEN, HIDDEN, QKV_LDB, HIDDEN, 0);

    // ---- KV projection: [6404,2048] ----
    gemm_bf16x3<<<dim3(KV_N / 128, (KV_LEN + 127) / 128), 256>>>(
        cross_hi, cross_lo, wqkv_hi, wqkv_lo, pkv,
        KV_LEN, HIDDEN, QKV_LDB, KV_N, NH * HD);

    // ---- RMS norms ----
    {
        int nwarps = Q_LEN * NH;
        rmsnorm_kernel<<<(nwarps * 32 + 255) / 256, 256>>>(pq, q_norm, Q_LEN, NH, HIDDEN);
    }
    {
        int nwarps = KV_LEN * NKVH;
        rmsnorm_kernel<<<(nwarps * 32 + 255) / 256, 256>>>(pkv, k_norm, KV_LEN, NKVH, KV_N);
    }

    // ---- attention ----
    {
        size_t smem = (size_t)(3 * 64 * KROW + 64 * 65 + 3 * 64) * sizeof(float);
        cudaFuncSetAttribute(attn_kernel, cudaFuncAttributeMaxDynamicSharedMemorySize,
                             (int)smem);
        attn_kernel<<<dim3(Q_LEN / 64, NH), 256, smem>>>(mask);
    }

    // ---- split attention output, O projection ----
    {
        int n4 = Q_LEN * HIDDEN / 4;
        split_kernel<<<(n4 + 255) / 256, 256>>>(pattn, attn_hi, attn_lo, n4);
    }
    gemm_bf16x3<<<dim3(HIDDEN / 128, Q_LEN / 128), 256>>>(
        attn_hi, attn_lo, wo_hi, wo_lo, out,
        Q_LEN, HIDDEN, HIDDEN, HIDDEN, 0);
}

// round 3
// speedup vs baseline: 2.6710x; 2.0292x over previous
#include <cuda_runtime.h>
#include <cuda_bf16.h>
#include <math.h>

#define Q_LEN   1024
#define KV_LEN  6404
#define KV_PAD  6464          // 101 * 64
#define HIDDEN  4096
#define NH      32
#define NKVH    8
#define HD      128
#define QKV_LDB 6144
#define KV_N    2048
#define ATTN_SCALE 0.08838834764831845f

// ---------------- scratch ----------------
__device__ float g_q[Q_LEN * HIDDEN];
__device__ float g_kv[KV_LEN * KV_N];

__device__ __nv_bfloat16 g_hid_hi[Q_LEN * HIDDEN];
__device__ __nv_bfloat16 g_hid_lo[Q_LEN * HIDDEN];
__device__ __nv_bfloat16 g_cross_hi[KV_LEN * HIDDEN];
__device__ __nv_bfloat16 g_cross_lo[KV_LEN * HIDDEN];
__device__ __nv_bfloat16 g_wqkvT_hi[QKV_LDB * HIDDEN];   // [col][k]
__device__ __nv_bfloat16 g_wqkvT_lo[QKV_LDB * HIDDEN];
__device__ __nv_bfloat16 g_woT_hi[HIDDEN * HIDDEN];
__device__ __nv_bfloat16 g_woT_lo[HIDDEN * HIDDEN];
__device__ __nv_bfloat16 g_qhi[Q_LEN * HIDDEN];
__device__ __nv_bfloat16 g_qlo[Q_LEN * HIDDEN];
__device__ __nv_bfloat16 g_khi[KV_LEN * (NKVH * HD)];
__device__ __nv_bfloat16 g_klo[KV_LEN * (NKVH * HD)];
__device__ __nv_bfloat16 g_vthi[NKVH * HD * KV_PAD];     // [kvh*128+d][kv]
__device__ __nv_bfloat16 g_vtlo[NKVH * HD * KV_PAD];
__device__ __nv_bfloat16 g_attnhi[Q_LEN * HIDDEN];
__device__ __nv_bfloat16 g_attnlo[Q_LEN * HIDDEN];

__device__ __forceinline__ void split2(float x, float y, unsigned& hi, unsigned& lo)
{
    __nv_bfloat16 hx = __float2bfloat16(x), hy = __float2bfloat16(y);
    float lx = x - __bfloat162float(hx), ly = y - __bfloat162float(hy);
    __nv_bfloat16 lxb = __float2bfloat16(lx), lyb = __float2bfloat16(ly);
    hi = (unsigned)__bfloat16_as_ushort(hx) | ((unsigned)__bfloat16_as_ushort(hy) << 16);
    lo = (unsigned)__bfloat16_as_ushort(lxb) | ((unsigned)__bfloat16_as_ushort(lyb) << 16);
}

// ---------------- fp32 -> bf16 hi/lo split (row-major copy) ----------------
__global__ void split_kernel(const float* __restrict__ x,
                             __nv_bfloat16* __restrict__ hi,
                             __nv_bfloat16* __restrict__ lo, int n4)
{
    int i = blockIdx.x * blockDim.x + threadIdx.x;
    if (i >= n4) return;
    float4 v = ((const float4*)x)[i];
    uint2 uh, ul;
    split2(v.x, v.y, uh.x, ul.x);
    split2(v.z, v.w, uh.y, ul.y);
    ((uint2*)hi)[i] = uh;
    ((uint2*)lo)[i] = ul;
}

// ---------------- fp32 [R][C] -> bf16 hi/lo [C][R] ----------------
__global__ void wtrans_split(const float* __restrict__ w,
                             __nv_bfloat16* __restrict__ hi,
                             __nv_bfloat16* __restrict__ lo, int R, int C)
{
    __shared__ float t[32][33];
    int tx = threadIdx.x, ty = threadIdx.y;
    int r0 = blockIdx.y * 32, c0 = blockIdx.x * 32;
#pragma unroll
    for (int i = 0; i < 4; i++)
        t[ty + 8 * i][tx] = w[(size_t)(r0 + ty + 8 * i) * C + c0 + tx];
    __syncthreads();
#pragma unroll
    for (int i = 0; i < 4; i++) {
        float v = t[tx][ty + 8 * i];
        __nv_bfloat16 hb = __float2bfloat16(v);
        __nv_bfloat16 lb = __float2bfloat16(v - __bfloat162float(hb));
        size_t off = (size_t)(c0 + ty + 8 * i) * R + r0 + tx;
        hi[off] = hb; lo[off] = lb;
    }
}

// ---------------- V: g_kv[:,1024+kvh*128+d] -> [kvh*128+d][kv] hi/lo ----------
__global__ void vtrans_split(const float* __restrict__ kv)
{
    __shared__ float t[32][33];
    int tx = threadIdx.x, ty = threadIdx.y;
    int kv0 = blockIdx.x * 32, d0 = blockIdx.y * 32, kvh = blockIdx.z;
#pragma unroll
    for (int i = 0; i < 4; i++) {
        int r = kv0 + ty + 8 * i;
        t[ty + 8 * i][tx] = (r < KV_LEN)
            ? kv[(size_t)r * KV_N + NKVH * HD + kvh * HD + d0 + tx] : 0.f;
    }
    __syncthreads();
#pragma unroll
    for (int i = 0; i < 4; i++) {
        float v = t[tx][ty + 8 * i];
        __nv_bfloat16 hb = __float2bfloat16(v);
        __nv_bfloat16 lb = __float2bfloat16(v - __bfloat162float(hb));
        size_t off = (size_t)(kvh * HD + d0 + ty + 8 * i) * KV_PAD + kv0 + tx;
        g_vthi[off] = hb; g_vtlo[off] = lb;
    }
}

// ---------------- RMS norm fp32 -> bf16 hi/lo ----------------
__global__ void rmsnorm_split(const float* __restrict__ x, const float* __restrict__ w,
                              __nv_bfloat16* __restrict__ hi, __nv_bfloat16* __restrict__ lo,
                              int nrows, int nheads, int ld_in, int ld_out)
{
    int gw = (int)((blockIdx.x * blockDim.x + threadIdx.x) >> 5);
    int lane = threadIdx.x & 31;
    if (gw >= nrows * nheads) return;
    int row = gw / nheads, h = gw - row * nheads;
    const float* p = x + (size_t)row * ld_in + h * HD;
    float4 v = *(const float4*)(p + lane * 4);
    float ss = v.x * v.x + v.y * v.y + v.z * v.z + v.w * v.w;
#pragma unroll
    for (int o = 16; o > 0; o >>= 1) ss += __shfl_xor_sync(0xffffffffu, ss, o);
    float s = rsqrtf(ss * (1.f / HD) + 1e-5f);
    float4 wv = *(const float4*)(w + lane * 4);
    v.x *= s * wv.x; v.y *= s * wv.y; v.z *= s * wv.z; v.w *= s * wv.w;
    uint2 uh, ul;
    split2(v.x, v.y, uh.x, ul.x);
    split2(v.z, v.w, uh.y, ul.y);
    size_t off = (size_t)row * ld_out + h * HD + lane * 4;
    *(uint2*)(hi + off) = uh;
    *(uint2*)(lo + off) = ul;
}

// ---------------- bf16x3 GEMM, B pre-transposed [n][k] ----------------
#define TS 40

#define MMA_BF16(d, a, b)                                                      \
    asm volatile(                                                              \
        "mma.sync.aligned.m16n8k16.row.col.f32.bf16.bf16.f32 "                 \
        "{%0,%1,%2,%3},{%4,%5,%6,%7},{%8,%9},{%0,%1,%2,%3};"                   \
        : "+f"((d)[0]), "+f"((d)[1]), "+f"((d)[2]), "+f"((d)[3])               \
        : "r"((a)[0]), "r"((a)[1]), "r"((a)[2]), "r"((a)[3]),                  \
          "r"((b)[0]), "r"((b)[1]))

__global__ void __launch_bounds__(256) gemm_bf16x3(
    const __nv_bfloat16* __restrict__ Ahi, const __nv_bfloat16* __restrict__ Alo,
    const __nv_bfloat16* __restrict__ Bthi, const __nv_bfloat16* __restrict__ Btlo,
    float* __restrict__ C, int M, int K, int ldc)
{
    __shared__ __nv_bfloat16 As[2][128 * TS];
    __shared__ __nv_bfloat16 Bs[2][128 * TS];

    const int tid  = threadIdx.x;
    const int warp = tid >> 5, lane = tid & 31;
    const int g = lane >> 2, tig = lane & 3;
    const int wm = warp & 1, wn = warp >> 1;
    const int row0 = blockIdx.y * 128, col0 = blockIdx.x * 128;
    const int rowbase = wm * 64, colbase = wn * 32;

    float acc[4][4][4];
#pragma unroll
    for (int i = 0; i < 4; i++)
#pragma unroll
        for (int j = 0; j < 4; j++)
#pragma unroll
            for (int t = 0; t < 4; t++) acc[i][j][t] = 0.f;

    for (int k0 = 0; k0 < K; k0 += 32) {
#pragma unroll
        for (int i = 0; i < 2; i++) {
            int f = tid + i * 256;
            int r = f >> 2, kq = (f & 3) * 8;
            uint4 vh = make_uint4(0, 0, 0, 0), vl = vh;
            if (row0 + r < M) {
                size_t off = (size_t)(row0 + r) * K + k0 + kq;
                vh = *(const uint4*)(Ahi + off);
                vl = *(const uint4*)(Alo + off);
            }
            *(uint4*)&As[0][r * TS + kq] = vh;
            *(uint4*)&As[1][r * TS + kq] = vl;
            size_t boff = (size_t)(col0 + r) * K + k0 + kq;
            *(uint4*)&Bs[0][r * TS + kq] = *(const uint4*)(Bthi + boff);
            *(uint4*)&Bs[1][r * TS + kq] = *(const uint4*)(Btlo + boff);
        }
        __syncthreads();

#pragma unroll
        for (int ks = 0; ks < 32; ks += 16) {
            unsigned ah[4][4], al[4][4], bh[4][2], bl[4][2];
#pragma unroll
            for (int am = 0; am < 4; am++) {
                int base = (rowbase + am * 16 + g) * TS + ks + tig * 2;
                ah[am][0] = *(const unsigned*)&As[0][base];
                ah[am][1] = *(const unsigned*)&As[0][base + 8 * TS];
                ah[am][2] = *(const unsigned*)&As[0][base + 8];
                ah[am][3] = *(const unsigned*)&As[0][base + 8 * TS + 8];
                al[am][0] = *(const unsigned*)&As[1][base];
                al[am][1] = *(const unsigned*)&As[1][base + 8 * TS];
                al[am][2] = *(const unsigned*)&As[1][base + 8];
                al[am][3] = *(const unsigned*)&As[1][base + 8 * TS + 8];
            }
#pragma unroll
            for (int an = 0; an < 4; an++) {
                int base = (colbase + an * 8 + g) * TS + ks + tig * 2;
                bh[an][0] = *(const unsigned*)&Bs[0][base];
                bh[an][1] = *(const unsigned*)&Bs[0][base + 8];
                bl[an][0] = *(const unsigned*)&Bs[1][base];
                bl[an][1] = *(const unsigned*)&Bs[1][base + 8];
            }
#pragma unroll
            for (int am = 0; am < 4; am++)
#pragma unroll
                for (int an = 0; an < 4; an++) MMA_BF16(acc[am][an], ah[am], bh[an]);
#pragma unroll
            for (int am = 0; am < 4; am++)
#pragma unroll
                for (int an = 0; an < 4; an++) MMA_BF16(acc[am][an], al[am], bh[an]);
#pragma unroll
            for (int am = 0; am < 4; am++)
#pragma unroll
                for (int an = 0; an < 4; an++) MMA_BF16(acc[am][an], ah[am], bl[an]);
        }
        __syncthreads();
    }

#pragma unroll
    for (int am = 0; am < 4; am++) {
#pragma unroll
        for (int an = 0; an < 4; an++) {
            int r = row0 + rowbase + am * 16 + g;
            int c = col0 + colbase + an * 8 + tig * 2;
            if (r < M)
                *(float2*)(C + (size_t)r * ldc + c) =
                    make_float2(acc[am][an][0], acc[am][an][1]);
            if (r + 8 < M)
                *(float2*)(C + (size_t)(r + 8) * ldc + c) =
                    make_float2(acc[am][an][2], acc[am][an][3]);
        }
    }
}

// ---------------- tensor-core flash attention, bf16x3 ----------------
// grid (8 q-tiles of 128, 32 heads), 256 threads (8 warps x 16 q-rows).
#define QST 136
#define KST 136
#define VST 72
#define ATTN_SMEM ((2*128*QST + 2*64*KST + 2*128*VST) * 2)

__global__ void __launch_bounds__(256, 1) attn_mma(const float* __restrict__ mask)
{
    extern __shared__ __nv_bfloat16 sm[];
    __nv_bfloat16* Qh = sm;
    __nv_bfloat16* Ql = Qh + 128 * QST;
    __nv_bfloat16* Kh = Ql + 128 * QST;
    __nv_bfloat16* Kl = Kh + 64 * KST;
    __nv_bfloat16* Vh = Kl + 64 * KST;
    __nv_bfloat16* Vl = Vh + 128 * VST;

    const int tid = threadIdx.x, warp = tid >> 5, lane = tid & 31;
    const int g = lane >> 2, tig = lane & 3;
    const int h = blockIdx.y, kvh = h >> 2;
    const int q0 = blockIdx.x * 128;
    const int wr = warp * 16;
    const int row0 = q0 + wr + g;

    // Q resident
#pragma unroll
    for (int it = 0; it < 8; it++) {
        int idx = tid + it * 256;
        int r = idx >> 4, c = (idx & 15) * 8;
        size_t off = (size_t)(q0 + r) * HIDDEN + h * HD + c;
        *(uint4*)&Qh[r * QST + c] = *(const uint4*)(g_qhi + off);
        *(uint4*)&Ql[r * QST + c] = *(const uint4*)(g_qlo + off);
    }

    float o[16][4];
#pragma unroll
    for (int n = 0; n < 16; n++)
#pragma unroll
        for (int t = 0; t < 4; t++) o[n][t] = 0.f;
    float m0 = -1e30f, m1 = -1e30f, l0 = 0.f, l1 = 0.f;

    for (int kv0 = 0; kv0 < KV_LEN; kv0 += 64) {
        __syncthreads();
#pragma unroll
        for (int it = 0; it < 4; it++) {
            int idx = tid + it * 256;
            int r = idx >> 4, c = (idx & 15) * 8;
            uint4 vh = make_uint4(0, 0, 0, 0), vl = vh;
            if (kv0 + r < KV_LEN) {
                size_t off = (size_t)(kv0 + r) * (NKVH * HD) + kvh * HD + c;
                vh = *(const uint4*)(g_khi + off);
                vl = *(const uint4*)(g_klo + off);
            }
            *(uint4*)&Kh[r * KST + c] = vh;
            *(uint4*)&Kl[r * KST + c] = vl;
        }
#pragma unroll
        for (int it = 0; it < 4; it++) {
            int idx = tid + it * 256;
            int d = idx >> 3, c = (idx & 7) * 8;
            size_t off = ((size_t)kvh * HD + d) * KV_PAD + kv0 + c;
            *(uint4*)&Vh[d * VST + c] = *(const uint4*)(g_vthi + off);
            *(uint4*)&Vl[d * VST + c] = *(const uint4*)(g_vtlo + off);
        }
        __syncthreads();

        // ---- S = Q K^T (bf16x3) ----
        float s[8][4];
#pragma unroll
        for (int j = 0; j < 8; j++)
#pragma unroll
            for (int c = 0; c < 4; c++) s[j][c] = 0.f;

#pragma unroll
        for (int kt = 0; kt < 8; kt++) {
            int ab = (wr + g) * QST + kt * 16 + tig * 2;
            unsigned ah[4], al[4];
            ah[0] = *(const unsigned*)&Qh[ab];
            ah[1] = *(const unsigned*)&Qh[ab + 8 * QST];
            ah[2] = *(const unsigned*)&Qh[ab + 8];
            ah[3] = *(const unsigned*)&Qh[ab + 8 * QST + 8];
            al[0] = *(const unsigned*)&Ql[ab];
            al[1] = *(const unsigned*)&Ql[ab + 8 * QST];
            al[2] = *(const unsigned*)&Ql[ab + 8];
            al[3] = *(const unsigned*)&Ql[ab + 8 * QST + 8];
#pragma unroll
            for (int j = 0; j < 8; j++) {
                int bb = (8 * j + g) * KST + kt * 16 + tig * 2;
                unsigned bh[2], bl[2];
                bh[0] = *(const unsigned*)&Kh[bb];
                bh[1] = *(const unsigned*)&Kh[bb + 8];
                bl[0] = *(const unsigned*)&Kl[bb];
                bl[1] = *(const unsigned*)&Kl[bb + 8];
                MMA_BF16(s[j], ah, bh);
                MMA_BF16(s[j], al, bh);
                MMA_BF16(s[j], ah, bl);
            }
        }

        // ---- scale + mask ----
        bool partial = (kv0 + 64 > KV_LEN);
        float rmax0 = -1e30f, rmax1 = -1e30f;
        if (!partial) {
#pragma unroll
            for (int j = 0; j < 8; j++) {
                int col = kv0 + 8 * j + tig * 2;
                const float* mp = mask + (size_t)row0 * KV_LEN + col;
                float2 mk0 = *(const float2*)mp;
                float2 mk1 = *(const float2*)(mp + (size_t)8 * KV_LEN);
                s[j][0] = fmaf(s[j][0], ATTN_SCALE, mk0.x);
                s[j][1] = fmaf(s[j][1], ATTN_SCALE, mk0.y);
                s[j][2] = fmaf(s[j][2], ATTN_SCALE, mk1.x);
                s[j][3] = fmaf(s[j][3], ATTN_SCALE, mk1.y);
                rmax0 = fmaxf(rmax0, fmaxf(s[j][0], s[j][1]));
                rmax1 = fmaxf(rmax1, fmaxf(s[j][2], s[j][3]));
            }
        } else {
#pragma unroll
            for (int j = 0; j < 8; j++) {
#pragma unroll
                for (int c = 0; c < 2; c++) {
                    int col = kv0 + 8 * j + tig * 2 + c;
                    if (col < KV_LEN) {
                        s[j][c]     = fmaf(s[j][c], ATTN_SCALE,
                                           mask[(size_t)row0 * KV_LEN + col]);
                        s[j][2 + c] = fmaf(s[j][2 + c], ATTN_SCALE,
                                           mask[(size_t)(row0 + 8) * KV_LEN + col]);
                    } else {
                        s[j][c] = -1e30f;
                        s[j][2 + c] = -1e30f;
                    }
                }
                rmax0 = fmaxf(rmax0, fmaxf(s[j][0], s[j][1]));
                rmax1 = fmaxf(rmax1, fmaxf(s[j][2], s[j][3]));
            }
        }
        rmax0 = fmaxf(rmax0, __shfl_xor_sync(0xffffffffu, rmax0, 1));
        rmax0 = fmaxf(rmax0, __shfl_xor_sync(0xffffffffu, rmax0, 2));
        rmax1 = fmaxf(rmax1, __shfl_xor_sync(0xffffffffu, rmax1, 1));
        rmax1 = fmaxf(rmax1, __shfl_xor_sync(0xffffffffu, rmax1, 2));

        float mn0 = fmaxf(m0, rmax0), mn1 = fmaxf(m1, rmax1);
        float f0 = __expf(m0 - mn0), f1 = __expf(m1 - mn1);
        m0 = mn0; m1 = mn1;

        float sum0 = 0.f, sum1 = 0.f;
#pragma unroll
        for (int j = 0; j < 8; j++) {
            s[j][0] = __expf(s[j][0] - mn0);
            s[j][1] = __expf(s[j][1] - mn0);
            s[j][2] = __expf(s[j][2] - mn1);
            s[j][3] = __expf(s[j][3] - mn1);
            sum0 += s[j][0] + s[j][1];
            sum1 += s[j][2] + s[j][3];
        }
        sum0 += __shfl_xor_sync(0xffffffffu, sum0, 1);
        sum0 += __shfl_xor_sync(0xffffffffu, sum0, 2);
        sum1 += __shfl_xor_sync(0xffffffffu, sum1, 1);
        sum1 += __shfl_xor_sync(0xffffffffu, sum1, 2);
        l0 = l0 * f0 + sum0;
        l1 = l1 * f1 + sum1;

#pragma unroll
        for (int n = 0; n < 16; n++) {
            o[n][0] *= f0; o[n][1] *= f0; o[n][2] *= f1; o[n][3] *= f1;
        }

        // ---- PV (P fragments built from S registers) ----
#pragma unroll
        for (int t = 0; t < 4; t++) {
            unsigned ph[4], pl[4];
            split2(s[2 * t][0],     s[2 * t][1],     ph[0], pl[0]);
            split2(s[2 * t][2],     s[2 * t][3],     ph[1], pl[1]);
            split2(s[2 * t + 1][0], s[2 * t + 1][1], ph[2], pl[2]);
            split2(s[2 * t + 1][2], s[2 * t + 1][3], ph[3], pl[3]);
#pragma unroll
            for (int n = 0; n < 16; n++) {
                int vb = (8 * n + g) * VST + t * 16 + tig * 2;
                unsigned bh[2], bl[2];
                bh[0] = *(const unsigned*)&Vh[vb];
                bh[1] = *(const unsigned*)&Vh[vb + 8];
                bl[0] = *(const unsigned*)&Vl[vb];
                bl[1] = *(const unsigned*)&Vl[vb + 8];
                MMA_BF16(o[n], ph, bh);
                MMA_BF16(o[n], pl, bh);
                MMA_BF16(o[n], ph, bl);
            }
        }
    }

    // ---- epilogue: write bf16 hi/lo directly ----
    float il0 = 1.f / l0, il1 = 1.f / l1;
#pragma unroll
    for (int n = 0; n < 16; n++) {
        unsigned h01, lo01, h23, lo23;
        split2(o[n][0] * il0, o[n][1] * il0, h01, lo01);
        split2(o[n][2] * il1, o[n][3] * il1, h23, lo23);
        size_t base = (size_t)row0 * HIDDEN + h * HD + 8 * n + tig * 2;
        *(unsigned*)(g_attnhi + base) = h01;
        *(unsigned*)(g_attnlo + base) = lo01;
        *(unsigned*)(g_attnhi + base + (size_t)8 * HIDDEN) = h23;
        *(unsigned*)(g_attnlo + base + (size_t)8 * HIDDEN) = lo23;
    }
}

// ---------------------------------------------------------------------------
extern "C" void kernel_launch(void* const* d_in, const int* in_sizes, int n_in,
                              void* d_out, int out_size)
{
    const float* hidden = (const float*)d_in[0];
    const float* cross  = (const float*)d_in[1];
    const float* mask   = (const float*)d_in[2];
    const float* w_qkv  = (const float*)d_in[3];
    const float* w_o    = (const float*)d_in[4];
    const float* q_norm = (const float*)d_in[5];
    const float* k_norm = (const float*)d_in[6];
    float* out = (float*)d_out;
    (void)in_sizes; (void)n_in; (void)out_size;

    float *pq, *pkv;
    cudaGetSymbolAddress((void**)&pq,  g_q);
    cudaGetSymbolAddress((void**)&pkv, g_kv);
    __nv_bfloat16 *hid_hi, *hid_lo, *cross_hi, *cross_lo;
    __nv_bfloat16 *wqkvT_hi, *wqkvT_lo, *woT_hi, *woT_lo;
    __nv_bfloat16 *qhi, *qlo, *khi, *klo, *attnhi, *attnlo;
    cudaGetSymbolAddress((void**)&hid_hi,   g_hid_hi);
    cudaGetSymbolAddress((void**)&hid_lo,   g_hid_lo);
    cudaGetSymbolAddress((void**)&cross_hi, g_cross_hi);
    cudaGetSymbolAddress((void**)&cross_lo, g_cross_lo);
    cudaGetSymbolAddress((void**)&wqkvT_hi, g_wqkvT_hi);
    cudaGetSymbolAddress((void**)&wqkvT_lo, g_wqkvT_lo);
    cudaGetSymbolAddress((void**)&woT_hi,   g_woT_hi);
    cudaGetSymbolAddress((void**)&woT_lo,   g_woT_lo);
    cudaGetSymbolAddress((void**)&qhi,      g_qhi);
    cudaGetSymbolAddress((void**)&qlo,      g_qlo);
    cudaGetSymbolAddress((void**)&khi,      g_khi);
    cudaGetSymbolAddress((void**)&klo,      g_klo);
    cudaGetSymbolAddress((void**)&attnhi,   g_attnhi);
    cudaGetSymbolAddress((void**)&attnlo,   g_attnlo);

    // activations split
    {
        int n4 = Q_LEN * HIDDEN / 4;
        split_kernel<<<(n4 + 255) / 256, 256>>>(hidden, hid_hi, hid_lo, n4);
        n4 = KV_LEN * HIDDEN / 4;
        split_kernel<<<(n4 + 255) / 256, 256>>>(cross, cross_hi, cross_lo, n4);
    }
    // weight transpose + split
    wtrans_split<<<dim3(QKV_LDB / 32, HIDDEN / 32), dim3(32, 8)>>>(
        w_qkv, wqkvT_hi, wqkvT_lo, HIDDEN, QKV_LDB);
    wtrans_split<<<dim3(HIDDEN / 32, HIDDEN / 32), dim3(32, 8)>>>(
        w_o, woT_hi, woT_lo, HIDDEN, HIDDEN);

    // Q projection
    gemm_bf16x3<<<dim3(HIDDEN / 128, Q_LEN / 128), 256>>>(
        hid_hi, hid_lo, wqkvT_hi, wqkvT_lo, pq, Q_LEN, HIDDEN, HIDDEN);
    // KV projection (cols 4096..6143 of w_qkv = rows 4096.. of w_qkvT)
    gemm_bf16x3<<<dim3(KV_N / 128, (KV_LEN + 127) / 128), 256>>>(
        cross_hi, cross_lo,
        wqkvT_hi + (size_t)(NH * HD) * HIDDEN, wqkvT_lo + (size_t)(NH * HD) * HIDDEN,
        pkv, KV_LEN, HIDDEN, KV_N);

    // RMS norms -> bf16 hi/lo
    {
        int nwarps = Q_LEN * NH;
        rmsnorm_split<<<(nwarps * 32 + 255) / 256, 256>>>(
            pq, q_norm, qhi, qlo, Q_LEN, NH, HIDDEN, HIDDEN);
        nwarps = KV_LEN * NKVH;
        rmsnorm_split<<<(nwarps * 32 + 255) / 256, 256>>>(
            pkv, k_norm, khi, klo, KV_LEN, NKVH, KV_N, NKVH * HD);
    }
    // V transpose + split
    vtrans_split<<<dim3(KV_PAD / 32, HD / 32, NKVH), dim3(32, 8)>>>(pkv);

    // attention
    cudaFuncSetAttribute(attn_mma, cudaFuncAttributeMaxDynamicSharedMemorySize,
                         ATTN_SMEM);
    attn_mma<<<dim3(Q_LEN / 128, NH), 256, ATTN_SMEM>>>(mask);

    // O projection
    gemm_bf16x3<<<dim3(HIDDEN / 128, Q_LEN / 128), 256>>>(
        attnhi, attnlo, woT_hi, woT_lo, out, Q_LEN, HIDDEN, HIDDEN);
}